// round 2
// baseline (speedup 1.0000x reference)
#include <cuda_runtime.h>
#include <cstdint>

// ---------------- problem dims ----------------
#define B_    64
#define T_    100
#define INF_  700
#define RED_  256
#define WID_  4096
#define CLS_  20
#define ROWS_ (B_*T_)          // 6400
#define KC_   1280             // conv im2col K (256*5)
#define NELEM_ (ROWS_*WID_)    // 26214400

// ---------------- scratch (static device globals; no alloc allowed) ----------------
__device__ unsigned g_absmax[4];
__device__ float g_qsp[RED_*INF_];
__device__ float g_qfc1[WID_*RED_];
__device__ float g_qfc2[CLS_*WID_];
__device__ float g_convWt[RED_*KC_];
__device__ float g_xp[ROWS_*RED_];
__device__ float g_x5[(size_t)ROWS_*KC_];
__device__ float g_co[ROWS_*RED_];
__device__ float g_wsum[B_*WID_];

// ---------------- threefry2x32 (JAX-compatible, partitionable mode) ----------------
__host__ __device__ constexpr unsigned rotl32(unsigned v, int s) {
    return (v << s) | (v >> (32 - s));
}
struct K2 { unsigned a, b; };
constexpr K2 tf_const(unsigned k0, unsigned k1, unsigned x0, unsigned x1) {
    unsigned ks2 = k0 ^ k1 ^ 0x1BD11BDAu;
    unsigned ks[3] = {k0, k1, ks2};
    x0 += k0; x1 += k1;
    const int R[20] = {13,15,26,6, 17,29,16,24, 13,15,26,6, 17,29,16,24, 13,15,26,6};
    for (int g = 0; g < 5; ++g) {
        for (int j = 0; j < 4; ++j) { x0 += x1; x1 = rotl32(x1, R[g*4+j]); x1 ^= x0; }
        x0 += ks[(g+1)%3];
        x1 += ks[(g+2)%3] + (unsigned)(g+1);
    }
    return K2{x0, x1};
}
// Partitionable threefry:
//   split(key, 2)[i] = threefry2x32(key, (0, i))  (both output lanes = the new key)
//   subkey used by the Knuth loop's first uniform = split(key(42))[1]
constexpr K2 SUBKEY = tf_const(0u, 42u, 0u, 1u);
constexpr unsigned SK0 = SUBKEY.a;
constexpr unsigned SK1 = SUBKEY.b;

__device__ __forceinline__ uint2 tf2x32(unsigned k0, unsigned k1, unsigned x0, unsigned x1) {
    unsigned ks2 = k0 ^ k1 ^ 0x1BD11BDAu;
    x0 += k0; x1 += k1;
#define TFR(r) { x0 += x1; x1 = __funnelshift_l(x1, x1, (r)); x1 ^= x0; }
    TFR(13) TFR(15) TFR(26) TFR(6)   x0 += k1;  x1 += ks2 + 1u;
    TFR(17) TFR(29) TFR(16) TFR(24)  x0 += ks2; x1 += k0  + 2u;
    TFR(13) TFR(15) TFR(26) TFR(6)   x0 += k0;  x1 += k1  + 3u;
    TFR(17) TFR(29) TFR(16) TFR(24)  x0 += k1;  x1 += ks2 + 4u;
    TFR(13) TFR(15) TFR(26) TFR(6)   x0 += ks2; x1 += k0  + 5u;
#undef TFR
    return make_uint2(x0, x1);
}

// partitionable random_bits(32): bits[i] = xor of both lanes of threefry(key, (hi(i), lo(i)))
__device__ __forceinline__ unsigned rbits32(unsigned idx) {
    uint2 r = tf2x32(SK0, SK1, 0u, idx);
    return r.x ^ r.y;
}

// ---------------- small kernels ----------------
__global__ void init_k() {
    if (threadIdx.x < 4) g_absmax[threadIdx.x] = 0u;
}

__global__ void absmax_k(const float* __restrict__ W, int n, int which) {
    float m = 0.0f;
    for (int i = blockIdx.x*blockDim.x + threadIdx.x; i < n; i += gridDim.x*blockDim.x)
        m = fmaxf(m, fabsf(W[i]));
    #pragma unroll
    for (int o = 16; o; o >>= 1) m = fmaxf(m, __shfl_xor_sync(0xffffffffu, m, o));
    if ((threadIdx.x & 31) == 0) atomicMax(&g_absmax[which], __float_as_uint(m));
}

__global__ void quant_k(const float* __restrict__ W, float* __restrict__ Q, int n, int which) {
    float scale = fmaxf(__fdiv_rn(__uint_as_float(g_absmax[which]), 7.0f), 1e-8f);
    int i = blockIdx.x*blockDim.x + threadIdx.x;
    if (i < n) Q[i] = __fmul_rn(rintf(__fdiv_rn(W[i], scale)), scale);
}

// conv_W (O,I,K5) row-major -> g_convWt[o][k*256+i]
__global__ void convT_k(const float* __restrict__ convW) {
    int idx = blockIdx.x*blockDim.x + threadIdx.x;
    if (idx >= RED_*KC_) return;
    int o = idx / KC_, rem = idx % KC_;
    int k = rem >> 8, i = rem & 255;
    g_convWt[idx] = convW[o*KC_ + i*5 + k];
}

// im2col: x5[r][k*256+i] = xp[b, t+k-2, i] (zero outside [0,T))
__global__ void im2col_k() {
    int idx = blockIdx.x*blockDim.x + threadIdx.x;
    if (idx >= ROWS_*KC_) return;
    int r = idx / KC_, rem = idx % KC_;
    int k = rem >> 8, i = rem & 255;
    int t = r % T_, b = r / T_;
    int ts = t + k - 2;
    g_x5[idx] = (ts >= 0 && ts < T_) ? g_xp[(b*T_ + ts)*RED_ + i] : 0.0f;
}

// ---------------- tiled fp32 GEMM: C[M,N] = epi(A[M,K] @ B[N,K]^T + bias) ----------------
#define BM 128
#define BN 64
#define BK 16
#define TM 8
#define TN 4

template<int EPI>
__global__ __launch_bounds__(256, 2)
void gemm_k(const float* __restrict__ A, const float* __restrict__ B,
            const float* __restrict__ bias, float* __restrict__ C,
            int M, int N, int K,
            const float* __restrict__ latent, const float* __restrict__ gainp,
            float* __restrict__ drv, float* __restrict__ spk)
{
    __shared__ float As[BK][BM];
    __shared__ float Bs[BK][BN];
    const int tid = threadIdx.x;
    const int tx = tid & 15, ty = tid >> 4;
    const int bm0 = blockIdx.y * BM, bn0 = blockIdx.x * BN;
    const int arow = tid >> 2;         // 0..63
    const int ac4  = (tid & 3) * 4;    // 0,4,8,12

    float acc[TM][TN];
    #pragma unroll
    for (int i = 0; i < TM; ++i)
        #pragma unroll
        for (int j = 0; j < TN; ++j) acc[i][j] = 0.0f;

    for (int k0 = 0; k0 < K; k0 += BK) {
        const int c = k0 + ac4;
        float4 av0, av1, bv;
        if (c < K) {
            av0 = *reinterpret_cast<const float4*>(A + (size_t)(bm0 + arow      ) * K + c);
            av1 = *reinterpret_cast<const float4*>(A + (size_t)(bm0 + arow + 64 ) * K + c);
            bv  = *reinterpret_cast<const float4*>(B + (size_t)(bn0 + arow      ) * K + c);
        } else {
            av0 = make_float4(0,0,0,0); av1 = av0; bv = av0;
        }
        __syncthreads();
        As[ac4+0][arow]    = av0.x; As[ac4+1][arow]    = av0.y;
        As[ac4+2][arow]    = av0.z; As[ac4+3][arow]    = av0.w;
        As[ac4+0][arow+64] = av1.x; As[ac4+1][arow+64] = av1.y;
        As[ac4+2][arow+64] = av1.z; As[ac4+3][arow+64] = av1.w;
        Bs[ac4+0][arow] = bv.x; Bs[ac4+1][arow] = bv.y;
        Bs[ac4+2][arow] = bv.z; Bs[ac4+3][arow] = bv.w;
        __syncthreads();
        #pragma unroll
        for (int kk = 0; kk < BK; ++kk) {
            float a[TM], b[TN];
            #pragma unroll
            for (int i = 0; i < TM; ++i) a[i] = As[kk][ty*TM + i];
            #pragma unroll
            for (int j = 0; j < TN; ++j) b[j] = Bs[kk][tx*TN + j];
            #pragma unroll
            for (int i = 0; i < TM; ++i)
                #pragma unroll
                for (int j = 0; j < TN; ++j) acc[i][j] += a[i]*b[j];
        }
    }

    if (EPI == 0) {
        // relu(acc + bias[n]) -> C
        const int nb = bn0 + tx*TN;
        float b0 = bias[nb+0], b1 = bias[nb+1], b2 = bias[nb+2], b3 = bias[nb+3];
        #pragma unroll
        for (int i = 0; i < TM; ++i) {
            int m = bm0 + ty*TM + i;
            float4 v;
            v.x = fmaxf(acc[i][0] + b0, 0.0f);
            v.y = fmaxf(acc[i][1] + b1, 0.0f);
            v.z = fmaxf(acc[i][2] + b2, 0.0f);
            v.w = fmaxf(acc[i][3] + b3, 0.0f);
            *reinterpret_cast<float4*>(C + (size_t)m*N + nb) = v;
        }
    } else {
        // softplus -> drive -> threefry Knuth-indicator spike
        const float gabs = fabsf(gainp[0]);
        const int nb = bn0 + tx*TN;
        float b0 = bias[nb+0], b1 = bias[nb+1], b2 = bias[nb+2], b3 = bias[nb+3];
        #pragma unroll
        for (int i = 0; i < TM; ++i) {
            int m = bm0 + ty*TM + i;
            float lat = latent[m % T_];
            float pr[TN] = { acc[i][0]+b0, acc[i][1]+b1, acc[i][2]+b2, acc[i][3]+b3 };
            float4 dv, sv;
            float* dvp = &dv.x; float* svp = &sv.x;
            #pragma unroll
            for (int j = 0; j < TN; ++j) {
                float pre = pr[j];
                float sp  = fmaxf(pre, 0.0f) + log1pf(expf(-fabsf(pre)));
                float d   = (sp * lat) * gabs;
                unsigned idx = (unsigned)m * (unsigned)WID_ + (unsigned)(nb + j);
                unsigned bits = rbits32(idx);
                float u = __uint_as_float((bits >> 9) | 0x3f800000u) - 1.0f;
                // Knuth path (lam<10): pois>=1 <=> log(u1) > -lam ; lam>=10: P(pois>=1)~1
                float spike = (d >= 10.0f) ? 1.0f : ((logf(u) > -d) ? 1.0f : 0.0f);
                dvp[j] = d; svp[j] = spike;
            }
            unsigned base = (unsigned)m * (unsigned)WID_ + (unsigned)nb;
            *reinterpret_cast<float4*>(drv + base) = dv;
            *reinterpret_cast<float4*>(spk + base) = sv;
        }
    }
}

// ---------------- decay-weighted temporal reduction ----------------
__global__ void weighted_k(const float* __restrict__ spikes) {
    __shared__ float decay[T_];
    int tid = threadIdx.x;
    if (tid < T_) decay[tid] = expf(-2.0f + (float)tid * (2.0f/99.0f));
    __syncthreads();
    int idx = blockIdx.x * blockDim.x + tid;   // over B*WID
    if (idx >= B_*WID_) return;
    int b = idx >> 12, w = idx & (WID_-1);
    const float* sp = spikes + (size_t)b*T_*WID_ + w;
    float s = 0.0f;
    #pragma unroll 4
    for (int t = 0; t < T_; ++t) s += sp[(size_t)t*WID_] * decay[t];
    g_wsum[idx] = s;
}

// ---------------- logits: (64,4096) @ (20,4096)^T + bias ----------------
__global__ void logits_k(const float* __restrict__ bias, float* __restrict__ out) {
    int bc = blockIdx.x;                 // 0..1279
    int b = bc / CLS_, c = bc % CLS_;
    const float* wr = g_wsum + (size_t)b*WID_;
    const float* fr = g_qfc2 + (size_t)c*WID_;
    float s = 0.0f;
    for (int i = threadIdx.x; i < WID_; i += 128) s += wr[i]*fr[i];
    #pragma unroll
    for (int o = 16; o; o >>= 1) s += __shfl_xor_sync(0xffffffffu, s, o);
    __shared__ float red[4];
    if ((threadIdx.x & 31) == 0) red[threadIdx.x >> 5] = s;
    __syncthreads();
    if (threadIdx.x == 0) out[bc] = (red[0]+red[1]+red[2]+red[3]) + bias[c];
}

// ---------------- launcher ----------------
extern "C" void kernel_launch(void* const* d_in, const int* in_sizes, int n_in,
                              void* d_out, int out_size) {
    (void)in_sizes; (void)n_in; (void)out_size;
    const float* x        = (const float*)d_in[0];
    const float* latent   = (const float*)d_in[1];
    const float* spatialW = (const float*)d_in[2];
    const float* spatialB = (const float*)d_in[3];
    const float* convW    = (const float*)d_in[4];
    const float* convB    = (const float*)d_in[5];
    const float* fc1W     = (const float*)d_in[6];
    const float* fc1B     = (const float*)d_in[7];
    const float* fc2W     = (const float*)d_in[8];
    const float* fc2B     = (const float*)d_in[9];
    const float* gain     = (const float*)d_in[10];

    float* out        = (float*)d_out;
    float* out_logits = out;
    float* out_spk    = out + (CLS_*B_);                 // 1280
    float* out_drv    = out + (CLS_*B_) + (size_t)NELEM_;

    float *qsp, *qfc1, *qfc2, *cwt, *xp, *x5, *co;
    cudaGetSymbolAddress((void**)&qsp,  g_qsp);
    cudaGetSymbolAddress((void**)&qfc1, g_qfc1);
    cudaGetSymbolAddress((void**)&qfc2, g_qfc2);
    cudaGetSymbolAddress((void**)&cwt,  g_convWt);
    cudaGetSymbolAddress((void**)&xp,   g_xp);
    cudaGetSymbolAddress((void**)&x5,   g_x5);
    cudaGetSymbolAddress((void**)&co,   g_co);

    init_k<<<1, 32>>>();
    absmax_k<<<128, 256>>>(spatialW, RED_*INF_,  0);
    absmax_k<<<256, 256>>>(fc1W,     WID_*RED_,  1);
    absmax_k<<<128, 256>>>(fc2W,     CLS_*WID_,  2);
    quant_k<<<(RED_*INF_ + 255)/256, 256>>>(spatialW, qsp,  RED_*INF_, 0);
    quant_k<<<(WID_*RED_ + 255)/256, 256>>>(fc1W,     qfc1, WID_*RED_, 1);
    quant_k<<<(CLS_*WID_ + 255)/256, 256>>>(fc2W,     qfc2, CLS_*WID_, 2);
    convT_k<<<(RED_*KC_ + 255)/256, 256>>>(convW);

    // GEMM1: xp = relu(x @ qsp^T + b)   M=6400 N=256 K=700
    gemm_k<0><<<dim3(RED_/BN, ROWS_/BM), 256>>>(x, qsp, spatialB, xp,
                                                ROWS_, RED_, INF_,
                                                nullptr, nullptr, nullptr, nullptr);
    im2col_k<<<(ROWS_*KC_ + 255)/256, 256>>>();
    // conv as GEMM: co = relu(x5 @ cwt^T + cb)   M=6400 N=256 K=1280
    gemm_k<0><<<dim3(RED_/BN, ROWS_/BM), 256>>>(x5, cwt, convB, co,
                                                ROWS_, RED_, KC_,
                                                nullptr, nullptr, nullptr, nullptr);
    // GEMM2 fused epilogue: drive + spikes   M=6400 N=4096 K=256
    gemm_k<1><<<dim3(WID_/BN, ROWS_/BM), 256>>>(co, qfc1, fc1B, nullptr,
                                                ROWS_, WID_, RED_,
                                                latent, gain, out_drv, out_spk);
    weighted_k<<<(B_*WID_ + 255)/256, 256>>>(out_spk);
    logits_k<<<B_*CLS_, 128>>>(fc2B, out_logits);
}